// round 8
// baseline (speedup 1.0000x reference)
#include <cuda_runtime.h>
#include <cuda_bf16.h>
#include <cstdint>
#include <cstddef>
#include <math.h>

// ---------------------------------------------------------------------------
// Problem constants
// ---------------------------------------------------------------------------
#define T_SEQ   2048
#define HID     256
#define GATES   1024      // 4*HID
#define IN_DIM  22
#define D_H1    1024
#define D_H2    512
#define D_H3    1024
#define NPAIRS  65536

#define SENTINEL 0xFFFFFFFFu

// ---------------------------------------------------------------------------
// Scratch (device globals — allocation is forbidden)
// ---------------------------------------------------------------------------
__device__ float g_PRE [4 * T_SEQ * GATES];    // per-seq precomputed input gates (reused L0/L1)
__device__ float g_h0  [2 * T_SEQ * 512];      // layer0 output [chain][t][dir*256+u]
__device__ float g_h1  [2 * T_SEQ * 512];      // layer1 output
__device__ float g_fc1 [2 * T_SEQ * D_H1];
__device__ float g_enc [2 * T_SEQ * D_H2];
__device__ float g_P   [2 * T_SEQ * D_H3];     // 0.5*enc@Ws.T + 0.5*b3
__device__ float g_Ws  [D_H3 * D_H2];          // W3[:, :H2] + W3[:, H2:]
__device__ float g_bs  [2 * GATES];            // bih1 + bhh1

// ---------------------------------------------------------------------------
// Re-sentinel the LSTM output buffers (runs inside the graph every replay)
// ---------------------------------------------------------------------------
__global__ void init_sent_kernel()
{
    unsigned idx = blockIdx.x * blockDim.x + threadIdx.x;
    const unsigned total = 2u * T_SEQ * 512u;
    if (idx < total) {
        ((unsigned*)g_h0)[idx] = SENTINEL;
        ((unsigned*)g_h1)[idx] = SENTINEL;
    }
}

// ---------------------------------------------------------------------------
// Layer-0 input gates: PRE[seq][t][g] = v[t].Wih0[d][g] + bih0[d][g]+bhh0[d][g]
// grid (4, 2048, 4), block 256
// ---------------------------------------------------------------------------
__global__ void pre0_kernel(const float* __restrict__ v_r,
                            const float* __restrict__ v_l,
                            const float* __restrict__ Wih0,
                            const float* __restrict__ bih0,
                            const float* __restrict__ bhh0)
{
    int g    = blockIdx.x * 256 + threadIdx.x;   // 0..1023
    int t    = blockIdx.y;
    int seq  = blockIdx.z;                        // chain*2 + dir
    int chain = seq >> 1, dir = seq & 1;

    __shared__ float vs[IN_DIM];
    const float* v = (chain ? v_l : v_r) + (size_t)t * IN_DIM;
    if (threadIdx.x < IN_DIM) vs[threadIdx.x] = v[threadIdx.x];
    __syncthreads();

    const float* wr = Wih0 + ((size_t)dir * GATES + g) * IN_DIM;
    float s = bih0[dir * GATES + g] + bhh0[dir * GATES + g];
#pragma unroll
    for (int k = 0; k < IN_DIM; k++) s = fmaf(wr[k], vs[k], s);
    g_PRE[((size_t)seq * T_SEQ + t) * GATES + g] = s;
}

// ---------------------------------------------------------------------------
// Combined layer-1 biases
// ---------------------------------------------------------------------------
__global__ void bsum_kernel(const float* __restrict__ bih1,
                            const float* __restrict__ bhh1)
{
    int i = blockIdx.x * 256 + threadIdx.x;
    if (i < 2 * GATES) g_bs[i] = bih1[i] + bhh1[i];
}

// ---------------------------------------------------------------------------
// Ws = W3[:, :H2] + W3[:, H2:]
// ---------------------------------------------------------------------------
__global__ void ws_kernel(const float* __restrict__ W3)
{
    int idx = blockIdx.x * 256 + threadIdx.x;
    if (idx < D_H3 * D_H2) {
        int i = idx >> 9;          // row (H3)
        int j = idx & 511;         // col (H2)
        g_Ws[idx] = W3[(size_t)i * (2 * D_H2) + j]
                  + W3[(size_t)i * (2 * D_H2) + D_H2 + j];
    }
}

// ---------------------------------------------------------------------------
// BiLSTM layer. grid = 32 (4 seqs x 8 chunk-CTAs), block 256, 1 CTA/SM.
// CTA c owns hidden units [32c,32c+32) = 128 gate rows; Whh slice lives in
// registers; per-step cross-CTA exchange via sentinel-polled L2 loads.
// ---------------------------------------------------------------------------
__global__ void __launch_bounds__(256, 1) lstm_kernel(
    const float* __restrict__ PRE,    // [4][T][1024]
    const float* __restrict__ Whh,    // [2][1024][256]
    float* __restrict__ HB)           // [2][T][512], sentinel-initialized
{
    const int bx    = blockIdx.x;
    const int seq   = bx >> 3;              // 0..3
    const int c     = bx & 7;               // chunk 0..7
    const int chain = seq >> 1, dir = seq & 1;
    const int tid   = threadIdx.x;
    const int rloc  = tid & 127;            // local gate row 0..127
    const int khalf = tid >> 7;             // K range [khalf*128, +128)
    const int gidx  = rloc >> 5;            // gate 0..3 (i,f,g,o)
    const int jl    = rloc & 31;            // hidden unit within chunk
    const int grow  = (gidx << 8) + (c << 5) + jl;   // global gate row

    __shared__ __align__(16) float h_s[256];
    __shared__ float part[256];
    __shared__ float gate_s[128];

    // Recurrent weights for this thread's (row, K-half) in registers.
    float w[128];
    {
        const float* wp = Whh + ((size_t)dir * GATES + grow) * HID + khalf * 128;
#pragma unroll
        for (int i = 0; i < 128; i += 4) {
            float4 v = *(const float4*)(wp + i);
            w[i] = v.x; w[i + 1] = v.y; w[i + 2] = v.z; w[i + 3] = v.w;
        }
    }

    float* hbc = HB + (size_t)chain * T_SEQ * 512;
    const float* prebase = PRE + (size_t)seq * T_SEQ * GATES;
    const int col  = dir * 256 + tid;          // h component this thread polls
    const bool own = ((tid >> 5) == c);        // produced by this CTA
    float cstate = 0.f;                        // valid for tid<32

    h_s[tid] = 0.f;                            // h_{-1} = 0
    __syncthreads();

    for (int t = 0; t < T_SEQ; t++) {
        const int t_act = dir ? (T_SEQ - 1 - t) : t;

        // Prefetch input-part (independent of h, overlaps the poll)
        float preval = 0.f;
        if (tid < 128)
            preval = __ldg(prebase + (size_t)t_act * GATES + grow);

        if (t > 0) {
            const int p_act = dir ? (t_act + 1) : (t_act - 1);
            if (!own) {
                const unsigned* pp =
                    (const unsigned*)(hbc + (size_t)p_act * 512 + col);
                unsigned v;
                do {
                    asm volatile("ld.volatile.global.u32 %0, [%1];"
                                 : "=r"(v) : "l"(pp));
                } while (v == SENTINEL);
                h_s[tid] = __uint_as_float(v);
            }
            __syncthreads();
        }

        // Partial matvec: 128 MACs/thread over smem-broadcast h
        const float* hp = h_s + khalf * 128;
        float a = 0.f;
#pragma unroll
        for (int i = 0; i < 128; i += 4) {
            float4 hv = *(const float4*)(hp + i);
            a = fmaf(w[i],     hv.x, a);
            a = fmaf(w[i + 1], hv.y, a);
            a = fmaf(w[i + 2], hv.z, a);
            a = fmaf(w[i + 3], hv.w, a);
        }
        part[tid] = a;
        __syncthreads();

        if (tid < 128) gate_s[tid] = preval + part[tid] + part[tid + 128];
        __syncthreads();

        if (tid < 32) {
            float gi = gate_s[tid];         // gate order i,f,g,o
            float gf = gate_s[32 + tid];
            float gg = gate_s[64 + tid];
            float go = gate_s[96 + tid];
            float si = 1.f / (1.f + expf(-gi));
            float sf = 1.f / (1.f + expf(-gf));
            float so = 1.f / (1.f + expf(-go));
            cstate = sf * cstate + si * tanhf(gg);
            float h = so * tanhf(cstate);
            h_s[(c << 5) + tid] = h;        // local copy for next step
            unsigned hv = __float_as_uint(h);
            unsigned* dst = (unsigned*)(hbc + (size_t)t_act * 512
                                        + dir * 256 + (c << 5) + tid);
            asm volatile("st.volatile.global.u32 [%0], %1;" :: "l"(dst), "r"(hv));
        }
        __syncthreads();
    }
}

// ---------------------------------------------------------------------------
// SGEMM: C[M,N] = act( alpha * ( A[M,K] @ B[N,K]^T + bias[N] ) )
// BM=BN=64, BK=16, 256 threads, 4x4 microtile. Requires M%64==N%64==K%16==0.
// ---------------------------------------------------------------------------
__global__ void __launch_bounds__(256) gemm_kernel(
    const float* __restrict__ A, const float* __restrict__ B,
    const float* __restrict__ bias, float* __restrict__ C,
    int M, int N, int K, float alpha, int relu)
{
    __shared__ __align__(16) float As[16][68];
    __shared__ __align__(16) float Bs[16][68];

    const int tid = threadIdx.x;
    const int tm = tid & 15, tn = tid >> 4;
    const int m0 = blockIdx.y * 64, n0 = blockIdx.x * 64;
    const int lr = tid & 63;            // row within tile
    const int lk = (tid >> 6) << 2;     // k offset {0,4,8,12}

    float acc[4][4];
#pragma unroll
    for (int i = 0; i < 4; i++)
#pragma unroll
        for (int j = 0; j < 4; j++) acc[i][j] = 0.f;

    const float* Ap = A + (size_t)(m0 + lr) * K + lk;
    const float* Bp = B + (size_t)(n0 + lr) * K + lk;

    for (int k0 = 0; k0 < K; k0 += 16) {
        float4 av = *(const float4*)(Ap + k0);
        float4 bv = *(const float4*)(Bp + k0);
        As[lk + 0][lr] = av.x; As[lk + 1][lr] = av.y;
        As[lk + 2][lr] = av.z; As[lk + 3][lr] = av.w;
        Bs[lk + 0][lr] = bv.x; Bs[lk + 1][lr] = bv.y;
        Bs[lk + 2][lr] = bv.z; Bs[lk + 3][lr] = bv.w;
        __syncthreads();

#pragma unroll
        for (int kk = 0; kk < 16; kk++) {
            float4 a4 = *(const float4*)&As[kk][tm << 2];
            float4 b4 = *(const float4*)&Bs[kk][tn << 2];
            float ar[4] = {a4.x, a4.y, a4.z, a4.w};
            float br[4] = {b4.x, b4.y, b4.z, b4.w};
#pragma unroll
            for (int i = 0; i < 4; i++)
#pragma unroll
                for (int j = 0; j < 4; j++)
                    acc[i][j] = fmaf(ar[i], br[j], acc[i][j]);
        }
        __syncthreads();
    }

    const int nb = n0 + (tn << 2);
    float bi[4];
#pragma unroll
    for (int j = 0; j < 4; j++) bi[j] = bias[nb + j];

#pragma unroll
    for (int i = 0; i < 4; i++) {
        int m = m0 + (tm << 2) + i;
        float4 o;
        float v0 = alpha * (acc[i][0] + bi[0]);
        float v1 = alpha * (acc[i][1] + bi[1]);
        float v2 = alpha * (acc[i][2] + bi[2]);
        float v3 = alpha * (acc[i][3] + bi[3]);
        if (relu) {
            v0 = fmaxf(v0, 0.f); v1 = fmaxf(v1, 0.f);
            v2 = fmaxf(v2, 0.f); v3 = fmaxf(v3, 0.f);
        }
        o.x = v0; o.y = v1; o.z = v2; o.w = v3;
        *(float4*)(C + (size_t)m * N + nb) = o;
    }
}

// ---------------------------------------------------------------------------
// Pair stage: logits[p] = relu(P_r[pr] + P_l[pl]) . Wout^T + bout; log_softmax
// ---------------------------------------------------------------------------
__global__ void __launch_bounds__(256) pair_kernel(
    const int* __restrict__ pair_r, const int* __restrict__ pair_l,
    const float* __restrict__ Wout, const float* __restrict__ bout,
    float* __restrict__ out)
{
    __shared__ float w0[D_H3], w1[D_H3];
    for (int i = threadIdx.x; i < D_H3; i += 256) {
        w0[i] = Wout[i];
        w1[i] = Wout[D_H3 + i];
    }
    __syncthreads();

    const int warp = threadIdx.x >> 5, lane = threadIdx.x & 31;
    const float b0 = bout[0], b1 = bout[1];
    const float* Pr_base = g_P;
    const float* Pl_base = g_P + (size_t)T_SEQ * D_H3;

    for (int p = blockIdx.x * 8 + warp; p < NPAIRS; p += gridDim.x * 8) {
        const float4* Pr = (const float4*)(Pr_base + (size_t)pair_r[p] * D_H3);
        const float4* Pl = (const float4*)(Pl_base + (size_t)pair_l[p] * D_H3);
        float a0 = 0.f, a1 = 0.f;
#pragma unroll 4
        for (int k4 = lane; k4 < D_H3 / 4; k4 += 32) {
            float4 r = __ldg(Pr + k4);
            float4 l = __ldg(Pl + k4);
            int kb = k4 << 2;
            float s0 = fmaxf(r.x + l.x, 0.f);
            float s1 = fmaxf(r.y + l.y, 0.f);
            float s2 = fmaxf(r.z + l.z, 0.f);
            float s3 = fmaxf(r.w + l.w, 0.f);
            a0 = fmaf(s0, w0[kb], a0);     a1 = fmaf(s0, w1[kb], a1);
            a0 = fmaf(s1, w0[kb + 1], a0); a1 = fmaf(s1, w1[kb + 1], a1);
            a0 = fmaf(s2, w0[kb + 2], a0); a1 = fmaf(s2, w1[kb + 2], a1);
            a0 = fmaf(s3, w0[kb + 3], a0); a1 = fmaf(s3, w1[kb + 3], a1);
        }
#pragma unroll
        for (int off = 16; off > 0; off >>= 1) {
            a0 += __shfl_down_sync(0xFFFFFFFFu, a0, off);
            a1 += __shfl_down_sync(0xFFFFFFFFu, a1, off);
        }
        if (lane == 0) {
            float l0 = a0 + b0, l1 = a1 + b1;
            float m = fmaxf(l0, l1);
            float lse = m + logf(expf(l0 - m) + expf(l1 - m));
            out[2 * p]     = l0 - lse;
            out[2 * p + 1] = l1 - lse;
        }
    }
}

// ---------------------------------------------------------------------------
// Host
// ---------------------------------------------------------------------------
static void launch_gemm(const float* A, const float* B, const float* bias,
                        float* C, int M, int N, int K, float alpha, int relu)
{
    dim3 grid(N / 64, M / 64);
    gemm_kernel<<<grid, 256>>>(A, B, bias, C, M, N, K, alpha, relu);
}

extern "C" void kernel_launch(void* const* d_in, const int* in_sizes, int n_in,
                              void* d_out, int out_size)
{
    const float* v_r    = (const float*)d_in[0];
    const float* v_l    = (const float*)d_in[1];
    const int*   pair_r = (const int*)  d_in[2];
    const int*   pair_l = (const int*)  d_in[3];
    const float* Wih0   = (const float*)d_in[4];
    const float* Whh0   = (const float*)d_in[5];
    const float* bih0   = (const float*)d_in[6];
    const float* bhh0   = (const float*)d_in[7];
    const float* Wih1   = (const float*)d_in[8];
    const float* Whh1   = (const float*)d_in[9];
    const float* bih1   = (const float*)d_in[10];
    const float* bhh1   = (const float*)d_in[11];
    const float* W1     = (const float*)d_in[12];
    const float* b1     = (const float*)d_in[13];
    const float* W2     = (const float*)d_in[14];
    const float* b2     = (const float*)d_in[15];
    const float* W3     = (const float*)d_in[16];
    const float* b3     = (const float*)d_in[17];
    const float* Wout   = (const float*)d_in[18];
    const float* bout   = (const float*)d_in[19];
    float* out = (float*)d_out;

    float *PRE, *H0, *H1, *FC1, *ENC, *PT, *WS, *BS;
    cudaGetSymbolAddress((void**)&PRE, g_PRE);
    cudaGetSymbolAddress((void**)&H0,  g_h0);
    cudaGetSymbolAddress((void**)&H1,  g_h1);
    cudaGetSymbolAddress((void**)&FC1, g_fc1);
    cudaGetSymbolAddress((void**)&ENC, g_enc);
    cudaGetSymbolAddress((void**)&PT,  g_P);
    cudaGetSymbolAddress((void**)&WS,  g_Ws);
    cudaGetSymbolAddress((void**)&BS,  g_bs);

    // 1. Sentinel-init LSTM output buffers (every replay)
    init_sent_kernel<<<(2 * T_SEQ * 512 + 255) / 256, 256>>>();

    // 2. Small precomputes
    pre0_kernel<<<dim3(4, T_SEQ, 4), 256>>>(v_r, v_l, Wih0, bih0, bhh0);
    bsum_kernel<<<8, 256>>>(bih1, bhh1);
    ws_kernel<<<(D_H3 * D_H2 + 255) / 256, 256>>>(W3);

    // 3. LSTM layer 0 (4 seqs x 8 chunk CTAs)
    lstm_kernel<<<32, 256>>>(PRE, Whh0, H0);

    // 4. Layer-1 input gates: PRE[seq] = h0_chain @ Wih1[dir]^T + (bih1+bhh1)
    for (int seq = 0; seq < 4; seq++) {
        int chain = seq >> 1, dir = seq & 1;
        launch_gemm(H0 + (size_t)chain * T_SEQ * 512,
                    Wih1 + (size_t)dir * GATES * 512,
                    BS + (size_t)dir * GATES,
                    PRE + (size_t)seq * T_SEQ * GATES,
                    T_SEQ, GATES, 512, 1.f, 0);
    }

    // 5. LSTM layer 1
    lstm_kernel<<<32, 256>>>(PRE, Whh1, H1);

    // 6. MLP encoders per chain
    for (int chain = 0; chain < 2; chain++) {
        launch_gemm(H1 + (size_t)chain * T_SEQ * 512, W1, b1,
                    FC1 + (size_t)chain * T_SEQ * D_H1,
                    T_SEQ, D_H1, 512, 1.f, 1);
        launch_gemm(FC1 + (size_t)chain * T_SEQ * D_H1, W2, b2,
                    ENC + (size_t)chain * T_SEQ * D_H2,
                    T_SEQ, D_H2, D_H1, 1.f, 1);
        // P = 0.5*(enc @ Ws^T + b3)
        launch_gemm(ENC + (size_t)chain * T_SEQ * D_H2, WS, b3,
                    PT + (size_t)chain * T_SEQ * D_H3,
                    T_SEQ, D_H3, D_H2, 0.5f, 0);
    }

    // 7. Pair gather + dot + log_softmax
    pair_kernel<<<2048, 256>>>(pair_r, pair_l, Wout, bout, out);
}

// round 9
// speedup vs baseline: 1.4182x; 1.4182x over previous
#include <cuda_runtime.h>
#include <cuda_bf16.h>
#include <cstdint>
#include <cstddef>
#include <math.h>

// ---------------------------------------------------------------------------
// Problem constants
// ---------------------------------------------------------------------------
#define T_SEQ   2048
#define HID     256
#define GATES   1024      // 4*HID
#define IN_DIM  22
#define D_H1    1024
#define D_H2    512
#define D_H3    1024
#define NPAIRS  65536

#define SENTINEL 0xFFFFFFFFu

// ---------------------------------------------------------------------------
// Scratch (device globals — allocation is forbidden)
// ---------------------------------------------------------------------------
__device__ float g_PRE [4 * T_SEQ * GATES];
__device__ float g_h0  [2 * T_SEQ * 512];
__device__ float g_h1  [2 * T_SEQ * 512];
__device__ float g_fc1 [2 * T_SEQ * D_H1];
__device__ float g_enc [2 * T_SEQ * D_H2];
__device__ float g_P   [2 * T_SEQ * D_H3];
__device__ float g_Ws  [D_H3 * D_H2];
__device__ float g_bs  [2 * GATES];

// ---------------------------------------------------------------------------
// Fast nonlinearities (MUFU-backed, ~1e-7 rel err)
// ---------------------------------------------------------------------------
__device__ __forceinline__ float sig_f(float x)
{
    return __fdividef(1.f, 1.f + __expf(-x));
}
__device__ __forceinline__ float tanh_f(float x)
{
    return __fdividef(2.f, 1.f + __expf(-2.f * x)) - 1.f;
}

// ---------------------------------------------------------------------------
// Re-sentinel the LSTM output buffers (inside the graph, every replay)
// ---------------------------------------------------------------------------
__global__ void init_sent_kernel()
{
    unsigned idx = blockIdx.x * blockDim.x + threadIdx.x;
    const unsigned total = 2u * T_SEQ * 512u;
    if (idx < total) {
        ((unsigned*)g_h0)[idx] = SENTINEL;
        ((unsigned*)g_h1)[idx] = SENTINEL;
    }
}

// ---------------------------------------------------------------------------
// Layer-0 input gates, 16 timesteps per CTA (weights register-resident).
// grid (4, 128, 4), block 256
// ---------------------------------------------------------------------------
__global__ void __launch_bounds__(256) pre0_kernel(
    const float* __restrict__ v_r, const float* __restrict__ v_l,
    const float* __restrict__ Wih0,
    const float* __restrict__ bih0, const float* __restrict__ bhh0)
{
    const int g     = blockIdx.x * 256 + threadIdx.x;   // 0..1023
    const int tbase = blockIdx.y * 16;
    const int seq   = blockIdx.z;
    const int chain = seq >> 1, dir = seq & 1;

    __shared__ float vs[16][IN_DIM + 2];
    const float* v = (chain ? v_l : v_r) + (size_t)tbase * IN_DIM;
    for (int i = threadIdx.x; i < 16 * IN_DIM; i += 256)
        vs[i / IN_DIM][i % IN_DIM] = v[i];
    __syncthreads();

    float wr[IN_DIM];
    const float* wp = Wih0 + ((size_t)dir * GATES + g) * IN_DIM;
#pragma unroll
    for (int k = 0; k < IN_DIM; k++) wr[k] = __ldg(wp + k);
    const float b = bih0[dir * GATES + g] + bhh0[dir * GATES + g];

    float* outp = g_PRE + ((size_t)seq * T_SEQ + tbase) * GATES + g;
#pragma unroll
    for (int tt = 0; tt < 16; tt++) {
        float s = b;
#pragma unroll
        for (int k = 0; k < IN_DIM; k++) s = fmaf(wr[k], vs[tt][k], s);
        outp[(size_t)tt * GATES] = s;
    }
}

// ---------------------------------------------------------------------------
// Combined layer-1 biases / Ws = W3[:, :H2] + W3[:, H2:]
// ---------------------------------------------------------------------------
__global__ void bsum_kernel(const float* __restrict__ bih1,
                            const float* __restrict__ bhh1)
{
    int i = blockIdx.x * 256 + threadIdx.x;
    if (i < 2 * GATES) g_bs[i] = bih1[i] + bhh1[i];
}

__global__ void ws_kernel(const float* __restrict__ W3)
{
    int idx = blockIdx.x * 256 + threadIdx.x;
    if (idx < D_H3 * D_H2) {
        int i = idx >> 9;
        int j = idx & 511;
        g_Ws[idx] = W3[(size_t)i * (2 * D_H2) + j]
                  + W3[(size_t)i * (2 * D_H2) + D_H2 + j];
    }
}

// ---------------------------------------------------------------------------
// BiLSTM layer. grid = 64 (4 seqs x 16 chunk-CTAs), block 256, 1 CTA/SM.
// CTA c owns hidden units [16c,16c+16) = 64 gate rows. Whh slice in regs
// (64 floats/thread, K split in quarters). Cross-CTA per-step exchange via
// sentinel-polled volatile L2 loads.
// ---------------------------------------------------------------------------
__global__ void __launch_bounds__(256, 1) lstm_kernel(
    const float* __restrict__ PRE,    // [4][T][1024]
    const float* __restrict__ Whh,    // [2][1024][256]
    float* __restrict__ HB)           // [2][T][512], sentinel-initialized
{
    const int bx    = blockIdx.x;
    const int seq   = bx >> 4;              // 0..3
    const int c     = bx & 15;              // chunk 0..15
    const int chain = seq >> 1, dir = seq & 1;
    const int tid   = threadIdx.x;
    const int rloc  = tid & 63;             // local gate row 0..63
    const int kq    = tid >> 6;             // K quarter 0..3
    const int gidx  = rloc >> 4;            // gate 0..3 (i,f,g,o)
    const int jl    = rloc & 15;            // hidden unit within chunk
    const int grow  = (gidx << 8) + (c << 4) + jl;   // global gate row

    __shared__ __align__(16) float h_s[256];
    __shared__ float part[256];
    __shared__ float gate_s[64];

    float w[64];
    {
        const float* wp = Whh + ((size_t)dir * GATES + grow) * HID + kq * 64;
#pragma unroll
        for (int i = 0; i < 64; i += 4) {
            float4 v = *(const float4*)(wp + i);
            w[i] = v.x; w[i + 1] = v.y; w[i + 2] = v.z; w[i + 3] = v.w;
        }
    }

    float* hbc = HB + (size_t)chain * T_SEQ * 512;
    const float* prebase = PRE + (size_t)seq * T_SEQ * GATES + grow;
    const int col  = dir * 256 + tid;        // polled h component
    const bool own = ((tid >> 4) == c);
    float cstate = 0.f;                      // valid for tid<16

    h_s[tid] = 0.f;
    __syncthreads();

    for (int t = 0; t < T_SEQ; t++) {
        const int t_act = dir ? (T_SEQ - 1 - t) : t;

        // Prefetch input-part (independent of h, overlaps the poll)
        float preval = 0.f;
        if (tid < 64)
            preval = __ldg(prebase + (size_t)t_act * GATES);

        if (t > 0) {
            const int p_act = dir ? (t_act + 1) : (t_act - 1);
            if (!own) {
                const unsigned* pp =
                    (const unsigned*)(hbc + (size_t)p_act * 512 + col);
                unsigned v;
                do {
                    asm volatile("ld.volatile.global.u32 %0, [%1];"
                                 : "=r"(v) : "l"(pp));
                } while (v == SENTINEL);
                h_s[tid] = __uint_as_float(v);
            }
            __syncthreads();
        }

        // Partial matvec: 64 MACs/thread over smem-broadcast h
        const float* hp = h_s + kq * 64;
        float a = 0.f;
#pragma unroll
        for (int i = 0; i < 64; i += 4) {
            float4 hv = *(const float4*)(hp + i);
            a = fmaf(w[i],     hv.x, a);
            a = fmaf(w[i + 1], hv.y, a);
            a = fmaf(w[i + 2], hv.z, a);
            a = fmaf(w[i + 3], hv.w, a);
        }
        part[tid] = a;
        __syncthreads();

        if (tid < 64)
            gate_s[tid] = preval + part[tid] + part[tid + 64]
                        + part[tid + 128] + part[tid + 192];
        __syncthreads();

        if (tid < 16) {
            float gi = gate_s[tid];
            float gf = gate_s[16 + tid];
            float gg = gate_s[32 + tid];
            float go = gate_s[48 + tid];
            cstate = sig_f(gf) * cstate + sig_f(gi) * tanh_f(gg);
            float h = sig_f(go) * tanh_f(cstate);
            h_s[(c << 4) + tid] = h;
            unsigned hv = __float_as_uint(h);
            unsigned* dst = (unsigned*)(hbc + (size_t)t_act * 512
                                        + dir * 256 + (c << 4) + tid);
            asm volatile("st.volatile.global.u32 [%0], %1;" :: "l"(dst), "r"(hv));
        }
        __syncthreads();
    }
}

// ---------------------------------------------------------------------------
// SGEMM: C = act( alpha * ( A[M,K] @ B[N,K]^T + bias[N] ) )
// 128x128 tile, BK=8, 256 threads, 8x8 microtile. Batched via blockIdx.z:
//   A += (z / aDiv)*sA;  B += (z % bMod)*sB;  bias += (z % bMod)*sBias;
//   C += z*sC
// ---------------------------------------------------------------------------
__global__ void __launch_bounds__(256) gemm_kernel(
    const float* __restrict__ A, const float* __restrict__ B,
    const float* __restrict__ bias, float* __restrict__ C,
    int M, int N, int K, float alpha, int relu,
    long sA, long sB, long sBias, long sC, int aDiv, int bMod)
{
    A    += (size_t)(blockIdx.z / aDiv) * sA;
    B    += (size_t)(blockIdx.z % bMod) * sB;
    bias += (size_t)(blockIdx.z % bMod) * sBias;
    C    += (size_t)blockIdx.z * sC;

    __shared__ __align__(16) float As[8][132];
    __shared__ __align__(16) float Bs[8][132];

    const int tid = threadIdx.x;
    const int tx = tid & 15, ty = tid >> 4;
    const int m0 = blockIdx.y * 128, n0 = blockIdx.x * 128;
    const int lrow = tid >> 1;
    const int lk   = (tid & 1) << 2;

    float acc[8][8];
#pragma unroll
    for (int i = 0; i < 8; i++)
#pragma unroll
        for (int j = 0; j < 8; j++) acc[i][j] = 0.f;

    const float* Ap = A + (size_t)(m0 + lrow) * K + lk;
    const float* Bp = B + (size_t)(n0 + lrow) * K + lk;

    for (int k0 = 0; k0 < K; k0 += 8) {
        float4 av = *(const float4*)(Ap + k0);
        float4 bv = *(const float4*)(Bp + k0);
        __syncthreads();
        As[lk + 0][lrow] = av.x; As[lk + 1][lrow] = av.y;
        As[lk + 2][lrow] = av.z; As[lk + 3][lrow] = av.w;
        Bs[lk + 0][lrow] = bv.x; Bs[lk + 1][lrow] = bv.y;
        Bs[lk + 2][lrow] = bv.z; Bs[lk + 3][lrow] = bv.w;
        __syncthreads();

#pragma unroll
        for (int kk = 0; kk < 8; kk++) {
            float4 a0 = *(const float4*)&As[kk][tx << 2];
            float4 a1 = *(const float4*)&As[kk][64 + (tx << 2)];
            float4 b0 = *(const float4*)&Bs[kk][ty << 2];
            float4 b1 = *(const float4*)&Bs[kk][64 + (ty << 2)];
            float ar[8] = {a0.x, a0.y, a0.z, a0.w, a1.x, a1.y, a1.z, a1.w};
            float br[8] = {b0.x, b0.y, b0.z, b0.w, b1.x, b1.y, b1.z, b1.w};
#pragma unroll
            for (int i = 0; i < 8; i++)
#pragma unroll
                for (int j = 0; j < 8; j++)
                    acc[i][j] = fmaf(ar[i], br[j], acc[i][j]);
        }
    }

    float bia[8];
#pragma unroll
    for (int j = 0; j < 8; j++) {
        int n = n0 + ((j < 4) ? (ty << 2) + j : 64 + (ty << 2) + (j - 4));
        bia[j] = bias[n];
    }

#pragma unroll
    for (int i = 0; i < 8; i++) {
        int m = m0 + ((i < 4) ? (tx << 2) + i : 64 + (tx << 2) + (i - 4));
        float v[8];
#pragma unroll
        for (int j = 0; j < 8; j++) {
            float x = alpha * (acc[i][j] + bia[j]);
            v[j] = relu ? fmaxf(x, 0.f) : x;
        }
        float4 o0 = {v[0], v[1], v[2], v[3]};
        float4 o1 = {v[4], v[5], v[6], v[7]};
        *(float4*)(C + (size_t)m * N + n0 + (ty << 2))      = o0;
        *(float4*)(C + (size_t)m * N + n0 + 64 + (ty << 2)) = o1;
    }
}

// ---------------------------------------------------------------------------
// Pair stage: logits[p] = relu(P_r[pr] + P_l[pl]) . Wout^T + bout; log_softmax
// ---------------------------------------------------------------------------
__global__ void __launch_bounds__(256) pair_kernel(
    const int* __restrict__ pair_r, const int* __restrict__ pair_l,
    const float* __restrict__ Wout, const float* __restrict__ bout,
    float* __restrict__ out)
{
    __shared__ float w0[D_H3], w1[D_H3];
    for (int i = threadIdx.x; i < D_H3; i += 256) {
        w0[i] = Wout[i];
        w1[i] = Wout[D_H3 + i];
    }
    __syncthreads();

    const int warp = threadIdx.x >> 5, lane = threadIdx.x & 31;
    const float b0 = bout[0], b1 = bout[1];
    const float* Pr_base = g_P;
    const float* Pl_base = g_P + (size_t)T_SEQ * D_H3;

    for (int p = blockIdx.x * 8 + warp; p < NPAIRS; p += gridDim.x * 8) {
        const float4* Pr = (const float4*)(Pr_base + (size_t)pair_r[p] * D_H3);
        const float4* Pl = (const float4*)(Pl_base + (size_t)pair_l[p] * D_H3);
        float a0 = 0.f, a1 = 0.f;
#pragma unroll 4
        for (int k4 = lane; k4 < D_H3 / 4; k4 += 32) {
            float4 r = __ldg(Pr + k4);
            float4 l = __ldg(Pl + k4);
            int kb = k4 << 2;
            float s0 = fmaxf(r.x + l.x, 0.f);
            float s1 = fmaxf(r.y + l.y, 0.f);
            float s2 = fmaxf(r.z + l.z, 0.f);
            float s3 = fmaxf(r.w + l.w, 0.f);
            a0 = fmaf(s0, w0[kb], a0);     a1 = fmaf(s0, w1[kb], a1);
            a0 = fmaf(s1, w0[kb + 1], a0); a1 = fmaf(s1, w1[kb + 1], a1);
            a0 = fmaf(s2, w0[kb + 2], a0); a1 = fmaf(s2, w1[kb + 2], a1);
            a0 = fmaf(s3, w0[kb + 3], a0); a1 = fmaf(s3, w1[kb + 3], a1);
        }
#pragma unroll
        for (int off = 16; off > 0; off >>= 1) {
            a0 += __shfl_down_sync(0xFFFFFFFFu, a0, off);
            a1 += __shfl_down_sync(0xFFFFFFFFu, a1, off);
        }
        if (lane == 0) {
            float l0 = a0 + b0, l1 = a1 + b1;
            float m = fmaxf(l0, l1);
            float lse = m + logf(expf(l0 - m) + expf(l1 - m));
            out[2 * p]     = l0 - lse;
            out[2 * p + 1] = l1 - lse;
        }
    }
}

// ---------------------------------------------------------------------------
// Host
// ---------------------------------------------------------------------------
extern "C" void kernel_launch(void* const* d_in, const int* in_sizes, int n_in,
                              void* d_out, int out_size)
{
    const float* v_r    = (const float*)d_in[0];
    const float* v_l    = (const float*)d_in[1];
    const int*   pair_r = (const int*)  d_in[2];
    const int*   pair_l = (const int*)  d_in[3];
    const float* Wih0   = (const float*)d_in[4];
    const float* Whh0   = (const float*)d_in[5];
    const float* bih0   = (const float*)d_in[6];
    const float* bhh0   = (const float*)d_in[7];
    const float* Wih1   = (const float*)d_in[8];
    const float* Whh1   = (const float*)d_in[9];
    const float* bih1   = (const float*)d_in[10];
    const float* bhh1   = (const float*)d_in[11];
    const float* W1     = (const float*)d_in[12];
    const float* b1     = (const float*)d_in[13];
    const float* W2     = (const float*)d_in[14];
    const float* b2     = (const float*)d_in[15];
    const float* W3     = (const float*)d_in[16];
    const float* b3     = (const float*)d_in[17];
    const float* Wout   = (const float*)d_in[18];
    const float* bout   = (const float*)d_in[19];
    float* out = (float*)d_out;

    float *PRE, *H0, *H1, *FC1, *ENC, *PT, *WS, *BS;
    cudaGetSymbolAddress((void**)&PRE, g_PRE);
    cudaGetSymbolAddress((void**)&H0,  g_h0);
    cudaGetSymbolAddress((void**)&H1,  g_h1);
    cudaGetSymbolAddress((void**)&FC1, g_fc1);
    cudaGetSymbolAddress((void**)&ENC, g_enc);
    cudaGetSymbolAddress((void**)&PT,  g_P);
    cudaGetSymbolAddress((void**)&WS,  g_Ws);
    cudaGetSymbolAddress((void**)&BS,  g_bs);

    // 1. Sentinel-init LSTM output buffers (every replay)
    init_sent_kernel<<<(2 * T_SEQ * 512 + 255) / 256, 256>>>();

    // 2. Small precomputes
    pre0_kernel<<<dim3(4, 128, 4), 256>>>(v_r, v_l, Wih0, bih0, bhh0);
    bsum_kernel<<<8, 256>>>(bih1, bhh1);
    ws_kernel<<<(D_H3 * D_H2 + 255) / 256, 256>>>(W3);

    // 3. LSTM layer 0 (4 seqs x 16 chunk CTAs)
    lstm_kernel<<<64, 256>>>(PRE, Whh0, H0);

    // 4. Layer-1 input gates, batched over seq (z=4):
    //    PRE[seq] = H0[chain] @ Wih1[dir]^T + (bih1+bhh1)[dir]
    gemm_kernel<<<dim3(GATES / 128, T_SEQ / 128, 4), 256>>>(
        H0, Wih1, BS, PRE, T_SEQ, GATES, 512, 1.f, 0,
        (long)T_SEQ * 512, (long)GATES * 512, (long)GATES,
        (long)T_SEQ * GATES, 2, 2);

    // 5. LSTM layer 1
    lstm_kernel<<<64, 256>>>(PRE, Whh1, H1);

    // 6. MLP encoders, batched over chain (z=2)
    gemm_kernel<<<dim3(D_H1 / 128, T_SEQ / 128, 2), 256>>>(
        H1, W1, b1, FC1, T_SEQ, D_H1, 512, 1.f, 1,
        (long)T_SEQ * 512, 0, 0, (long)T_SEQ * D_H1, 1, 1);

    gemm_kernel<<<dim3(D_H2 / 128, T_SEQ / 128, 2), 256>>>(
        FC1, W2, b2, ENC, T_SEQ, D_H2, D_H1, 1.f, 1,
        (long)T_SEQ * D_H1, 0, 0, (long)T_SEQ * D_H2, 1, 1);

    // P = 0.5*(enc @ Ws^T + b3)
    gemm_kernel<<<dim3(D_H3 / 128, T_SEQ / 128, 2), 256>>>(
        ENC, WS, b3, PT, T_SEQ, D_H3, D_H2, 0.5f, 0,
        (long)T_SEQ * D_H2, 0, 0, (long)T_SEQ * D_H3, 1, 1);

    // 7. Pair gather + dot + log_softmax
    pair_kernel<<<2048, 256>>>(pair_r, pair_l, Wout, bout, out);
}